// round 4
// baseline (speedup 1.0000x reference)
#include <cuda_runtime.h>

// Problem constants (fixed by the reference)
constexpr int H_   = 1024;
constexpr int W_   = 1024;
constexpr int FID_ = 100;
constexpr int NF_  = 8;
constexpr int NPTS = 1 << 20;
constexpr int KST  = 20;
constexpr int REP  = 2;            // accumulator replication factor
constexpr int NCHUNK = 4;          // flame split into 4 launches (profiling + tail)

// Replicated pixel-interleaved accumulator: REP planes of [H*W] float4.
// 32 MB total — resident in L2; planar so a hot pixel's replicas hash to
// different LTS slices (halves per-address/per-slice atomic serialization).
__device__ float4 g_acc[REP * H_ * W_];

__device__ __forceinline__ void red_add_v4(float4* addr, float4 v) {
    // sm_90+ vector float reduction: one L2 atomic op for all 4 channels.
    asm volatile("red.global.add.v4.f32 [%0], {%1,%2,%3,%4};"
                 :: "l"(addr), "f"(v.x), "f"(v.y), "f"(v.z), "f"(v.w)
                 : "memory");
}

__global__ __launch_bounds__(256) void flame_kernel(
    const float* __restrict__ points,      // [NPTS,3] (x,y,c)
    const int*   __restrict__ choices,     // [KST, NPTS]
    const float* __restrict__ A,           // [NF,2,2]
    const float* __restrict__ Bv,          // [NF,2]
    const float* __restrict__ fcol,        // [NF]
    const float* __restrict__ pal,         // [FID+1,4]
    const float* __restrict__ minv,        // [2]
    const float* __restrict__ rngv,        // [2]
    const int*   __restrict__ skipp,       // [1]
    int n0)                                // point-range offset for this chunk
{
    __shared__ float4 sA[NF_];             // a00,a01,a10,a11
    __shared__ float4 sBC[NF_];            // bx,by,func_color,unused
    __shared__ float4 sP[FID_ + 1];

    const int t = threadIdx.x;
    if (t < NF_) {
        sA[t]  = make_float4(A[4*t], A[4*t+1], A[4*t+2], A[4*t+3]);
        sBC[t] = make_float4(Bv[2*t], Bv[2*t+1], fcol[t], 0.f);
    }
    for (int i = t; i <= FID_; i += blockDim.x)
        sP[i] = make_float4(pal[4*i], pal[4*i+1], pal[4*i+2], pal[4*i+3]);

    const float mnx = minv[0], mny = minv[1];
    const float rx  = rngv[0], ry  = rngv[1];
    const int skip  = skipp[0];
    __syncthreads();

    const int n = n0 + blockIdx.x * blockDim.x + t;
    float x = points[3*n + 0];
    float y = points[3*n + 1];
    float c = points[3*n + 2];

    // Per-warp replica plane: spreads hot-pixel atomics across 2 L2 slices.
    const int plane = ((blockIdx.x ^ (t >> 5)) & (REP - 1)) * (H_ * W_);

    #pragma unroll
    for (int k = 0; k < KST; k++) {
        // Per-iteration load (NOT front-batched: batching 20 LDGs inflated
        // MLP_p1 and caused cross-CTA L1tex-queue spread — R2 regression).
        const int idx    = choices[k * NPTS + n];
        const float4 a   = sA[idx];
        const float4 bfc = sBC[idx];
        // Keep the exact FP expression order of the passing kernel.
        const float nx = a.x * x + a.y * y + bfc.x;
        const float ny = a.z * x + a.w * y + bfc.y;
        c = 0.5f * (c + bfc.z);
        x = nx; y = ny;

        if (k < skip) continue;

        // Matches XLA astype(int32): truncate toward zero, saturating, NaN->0.
        const int xb = (int)((x - mnx) * rx);
        const int yb = (int)((y - mny) * ry);
        if ((unsigned)xb < (unsigned)W_ && (unsigned)yb < (unsigned)H_) {
            const float _c = c * (float)FID_;
            const float cf = floorf(_c);
            const float t1 = _c - cf;
            const float t0 = 1.0f - t1;
            int cfi = (int)cf;        cfi = max(0, min(FID_, cfi));
            int cci = (int)ceilf(_c); cci = max(0, min(FID_, cci));
            const float4 p0 = sP[cfi];
            const float4 p1 = sP[cci];
            float4 v;
            v.x = t1 * p1.x + t0 * p0.x;
            v.y = t1 * p1.y + t0 * p0.y;
            v.z = t1 * p1.z + t0 * p0.z;
            v.w = t1 * p1.w + t0 * p0.w;
            // img[:, xb, yb]: xb indexes dim of size H (stride W), yb last dim
            red_add_v4(&g_acc[plane + xb * W_ + yb], v);
        }
    }
}

__global__ __launch_bounds__(256) void finalize_kernel(
    const float* __restrict__ raw0,
    float* __restrict__ out) {
    const int p = blockIdx.x * blockDim.x + threadIdx.x;
    const float4 v0 = g_acc[p];
    const float4 v1 = g_acc[H_ * W_ + p];
    out[p + 0 * H_ * W_] = (v0.x + v1.x) + raw0[p + 0 * H_ * W_];
    out[p + 1 * H_ * W_] = (v0.y + v1.y) + raw0[p + 1 * H_ * W_];
    out[p + 2 * H_ * W_] = (v0.z + v1.z) + raw0[p + 2 * H_ * W_];
    out[p + 3 * H_ * W_] = (v0.w + v1.w) + raw0[p + 3 * H_ * W_];
}

extern "C" void kernel_launch(void* const* d_in, const int* in_sizes, int n_in,
                              void* d_out, int out_size) {
    const float* points = (const float*)d_in[0];
    const int*   choices= (const int*)  d_in[1];
    const float* A      = (const float*)d_in[2];
    const float* b      = (const float*)d_in[3];
    const float* fcol   = (const float*)d_in[4];
    const float* pal    = (const float*)d_in[5];
    const float* minv   = (const float*)d_in[6];
    const float* rngv   = (const float*)d_in[7];
    const float* raw0   = (const float*)d_in[8];
    const int*   skip   = (const int*)  d_in[9];
    float* out = (float*)d_out;

    // Graph-capturable memset node; g_acc is a __device__ global (no allocs).
    void* acc_ptr = nullptr;
    cudaGetSymbolAddress(&acc_ptr, g_acc);
    cudaMemsetAsync(acc_ptr, 0, sizeof(float4) * REP * H_ * W_);

    // Flame split into 4 point-range chunks: perf-neutral (points independent)
    // and puts a flame chunk at kernel-launch index 5 so ncu (-s 5 -c 1)
    // finally profiles the dominant kernel.
    constexpr int CH = NPTS / NCHUNK;
    for (int i = 0; i < NCHUNK; i++)
        flame_kernel<<<CH / 256, 256>>>(points, choices, A, b, fcol, pal,
                                        minv, rngv, skip, i * CH);

    finalize_kernel<<<(H_ * W_) / 256, 256>>>(raw0, out);
}

// round 5
// speedup vs baseline: 1.1328x; 1.1328x over previous
#include <cuda_runtime.h>

// Problem constants (fixed by the reference)
constexpr int H_   = 1024;
constexpr int W_   = 1024;
constexpr int FID_ = 100;
constexpr int NF_  = 8;
constexpr int NPTS = 1 << 20;
constexpr int KST  = 20;

// Pixel-interleaved accumulator: [H*W] x float4 (channels 0..3). 16 MB,
// L2-resident; __device__ global (no allocs allowed).
__device__ float4 g_acc[H_ * W_];

__device__ __forceinline__ void red_add_v4(float4* addr, float4 v) {
    // sm_90+ vector float reduction: one op for all 4 channels.
    asm volatile("red.global.add.v4.f32 [%0], {%1,%2,%3,%4};"
                 :: "l"(addr), "f"(v.x), "f"(v.y), "f"(v.z), "f"(v.w)
                 : "memory");
}

__global__ __launch_bounds__(256) void flame_kernel(
    const float* __restrict__ points,      // [NPTS,3] (x,y,c)
    const int*   __restrict__ choices,     // [KST, NPTS]
    const float* __restrict__ A,           // [NF,2,2]
    const float* __restrict__ Bv,          // [NF,2]
    const float* __restrict__ fcol,        // [NF]
    const float* __restrict__ pal,         // [FID+1,4]
    const float* __restrict__ minv,        // [2]
    const float* __restrict__ rngv,        // [2]
    const int*   __restrict__ skipp)       // [1]
{
    __shared__ float4 sA[NF_];             // a00,a01,a10,a11
    __shared__ float4 sBC[NF_];            // bx,by,func_color,unused
    __shared__ float4 sP[FID_ + 1];

    const int t = threadIdx.x;
    if (t < NF_) {
        sA[t]  = make_float4(A[4*t], A[4*t+1], A[4*t+2], A[4*t+3]);
        sBC[t] = make_float4(Bv[2*t], Bv[2*t+1], fcol[t], 0.f);
    }
    for (int i = t; i <= FID_; i += blockDim.x)
        sP[i] = make_float4(pal[4*i], pal[4*i+1], pal[4*i+2], pal[4*i+3]);

    const float mnx = minv[0], mny = minv[1];
    const float rx  = rngv[0], ry  = rngv[1];
    const int skip  = skipp[0];
    __syncthreads();

    const int n = blockIdx.x * blockDim.x + t;
    float x = points[3*n + 0];
    float y = points[3*n + 1];
    float c = points[3*n + 2];

    #pragma unroll
    for (int k = 0; k < KST; k++) {
        // Per-iteration coalesced load (front-batching regressed: MLP_p1
        // inflation -> cross-CTA L1tex-queue spread, R2 post-mortem).
        const int idx    = choices[k * NPTS + n];
        const float4 a   = sA[idx];
        const float4 bfc = sBC[idx];
        // Exact FP expression order of the passing kernel — do not reassociate.
        const float nx = a.x * x + a.y * y + bfc.x;
        const float ny = a.z * x + a.w * y + bfc.y;
        c = 0.5f * (c + bfc.z);
        x = nx; y = ny;

        if (k < skip) continue;

        // Matches XLA astype(int32): truncate toward zero, saturating, NaN->0.
        const int xb = (int)((x - mnx) * rx);
        const int yb = (int)((y - mny) * ry);
        if ((unsigned)xb < (unsigned)W_ && (unsigned)yb < (unsigned)H_) {
            const float _c = c * (float)FID_;
            const float cf = floorf(_c);
            const float t1 = _c - cf;
            const float t0 = 1.0f - t1;
            int cfi = (int)cf;        cfi = max(0, min(FID_, cfi));
            int cci = (int)ceilf(_c); cci = max(0, min(FID_, cci));
            const float4 p0 = sP[cfi];
            const float4 p1 = sP[cci];
            float4 v;
            v.x = t1 * p1.x + t0 * p0.x;
            v.y = t1 * p1.y + t0 * p0.y;
            v.z = t1 * p1.z + t0 * p0.z;
            v.w = t1 * p1.w + t0 * p0.w;
            // img[:, xb, yb]: xb indexes dim of size H (stride W), yb last dim
            red_add_v4(&g_acc[xb * W_ + yb], v);
        }
    }
}

// 4 pixels per thread, all 128-bit memory ops (acc: 64B contiguous; raw0/out:
// one float4 per channel). Traffic floor 48MB -> ~6.5us.
__global__ __launch_bounds__(256) void finalize_kernel(
    const float* __restrict__ raw0,
    float* __restrict__ out) {
    const int p4 = blockIdx.x * blockDim.x + threadIdx.x;   // pixel group
    const int p  = p4 * 4;
    const float4 a0 = g_acc[p + 0];
    const float4 a1 = g_acc[p + 1];
    const float4 a2 = g_acc[p + 2];
    const float4 a3 = g_acc[p + 3];
    const float4* r = (const float4*)raw0;
    float4*       o = (float4*)out;
    constexpr int HW4 = (H_ * W_) / 4;
    float4 r0 = r[0 * HW4 + p4];
    float4 r1 = r[1 * HW4 + p4];
    float4 r2 = r[2 * HW4 + p4];
    float4 r3 = r[3 * HW4 + p4];
    o[0 * HW4 + p4] = make_float4(a0.x + r0.x, a1.x + r0.y, a2.x + r0.z, a3.x + r0.w);
    o[1 * HW4 + p4] = make_float4(a0.y + r1.x, a1.y + r1.y, a2.y + r1.z, a3.y + r1.w);
    o[2 * HW4 + p4] = make_float4(a0.z + r2.x, a1.z + r2.y, a2.z + r2.z, a3.z + r2.w);
    o[3 * HW4 + p4] = make_float4(a0.w + r3.x, a1.w + r3.y, a2.w + r3.z, a3.w + r3.w);
}

extern "C" void kernel_launch(void* const* d_in, const int* in_sizes, int n_in,
                              void* d_out, int out_size) {
    const float* points = (const float*)d_in[0];
    const int*   choices= (const int*)  d_in[1];
    const float* A      = (const float*)d_in[2];
    const float* b      = (const float*)d_in[3];
    const float* fcol   = (const float*)d_in[4];
    const float* pal    = (const float*)d_in[5];
    const float* minv   = (const float*)d_in[6];
    const float* rngv   = (const float*)d_in[7];
    const float* raw0   = (const float*)d_in[8];
    const int*   skip   = (const int*)  d_in[9];
    float* out = (float*)d_out;

    // Graph-capturable memset node; g_acc is a __device__ global (no allocs).
    void* acc_ptr = nullptr;
    cudaGetSymbolAddress(&acc_ptr, g_acc);
    cudaMemsetAsync(acc_ptr, 0, sizeof(float4) * H_ * W_);

    // Single flame launch: multi-wave grid (4096 CTAs) lets work-stealing
    // smooth per-CTA spread; sequential chunking exposed 4 tails (R3 lesson).
    flame_kernel<<<NPTS / 256, 256>>>(points, choices, A, b, fcol, pal,
                                      minv, rngv, skip);

    finalize_kernel<<<(H_ * W_ / 4) / 256, 256>>>(raw0, out);
}